// round 15
// baseline (speedup 1.0000x reference)
#include <cuda_runtime.h>
#include <math.h>

// ---------------- problem constants ----------------
#define Bz   64
#define PANO 36
#define OBJ  36
#define CFG  16
#define LM   8
#define IMG  32
#define Dd   300
#define Hh   512
#define EMB  64
#define ANG  128
#define FEAT 2176
#define TOPN 3
#define Mm   128
#define FEAT_ALL 3076     // FEAT + TOPN*D
#define XDIM 3140         // EMB + FEAT_ALL
#define G4   2048         // 4*H
#define CAND_ALL 3097     // FEAT + TOPN*7 + TOPN*D
#define CAND_PAD 3104     // padded to /4
#define EPSV 1e-8f

#define F4A  769          // FEAT_ALL/4
#define F4F  544          // FEAT/4
#define F4P  225          // TOPN*Dd/4
#define D4   75           // Dd/4

typedef unsigned long long ull;

// ---------------- scratch ----------------
__device__ int   g_top_idx[Bz * TOPN];
__device__ int   g_ctop[Bz * TOPN];
__device__ float g_land_sel[Bz * TOPN * Dd];
__device__ float g_land_norm[Bz * TOPN];
__device__ float g_cland[Bz * TOPN * Dd];
__device__ float g_cland_norm[Bz * TOPN];
__device__ float g_lrel[Bz * TOPN * 6];
__device__ float g_rmask[Bz * TOPN];
__device__ float g_pano_sim[(size_t)Bz * PANO * TOPN * Dd];
__device__ float g_q_feat[Bz * FEAT_ALL];
__device__ float g_aval[Bz * PANO];
__device__ float g_x[Bz * XDIM];
__device__ float g_cat[Bz * 2 * Hh];
__device__ float g_q_cand[Bz * CAND_PAD];
__device__ float g_part[5505024];   // split-K partials

// ---------------- helpers ----------------
__device__ __forceinline__ float warp_sum(float v) {
    #pragma unroll
    for (int off = 16; off > 0; off >>= 1) v += __shfl_xor_sync(0xffffffffu, v, off);
    return v;
}
__device__ __forceinline__ float sigmoidf(float x) { return 1.0f / (1.0f + expf(-x)); }
__device__ __forceinline__ float dot4(float4 a, float4 b) {
    return a.x * b.x + a.y * b.y + a.z * b.z + a.w * b.w;
}
__device__ __forceinline__ float4 f4add(float4 a, float4 b) {
    return make_float4(a.x + b.x, a.y + b.y, a.z + b.z, a.w + b.w);
}
// ---- packed f32x2 (sm_103a FFMA2) ----
__device__ __forceinline__ ull bcast2(float v) {
    ull r;
    asm("mov.b64 %0, {%1, %1};" : "=l"(r) : "f"(v));
    return r;
}
__device__ __forceinline__ void fma2(ull& acc, ull a, ull b) {
    asm("fma.rn.f32x2 %0, %1, %2, %0;" : "+l"(acc) : "l"(a), "l"(b));
}
__device__ __forceinline__ float2 u2f(ull u) {
    float2 f;
    asm("mov.b64 {%0, %1}, %2;" : "=f"(f.x), "=f"(f.y) : "l"(u));
    return f;
}
#define ULO(v4) (*(const ull*)&(v4).x)
#define UHI(v4) (*(const ull*)&(v4).z)

// ================= GEMM body (shared by single & dual wrappers) =================
#define ASTRIDE 72
template<int KT, bool VECW>
__device__ __forceinline__ void gemm_body(
    const float* __restrict__ A, const float* __restrict__ W, float* __restrict__ part,
    int K, int N, int Nck, int Np, int kbeg, int kend, int jtile, int sidx)
{
    __shared__ float As[2][KT][ASTRIDE];
    __shared__ float Ws[2][KT][128];
    const int tid = threadIdx.x;
    const int tx = tid & 15, ty = tid >> 4;
    const int nk = (kend - kbeg + KT - 1) / KT;

    constexpr int KQ = KT / 4;
    constexpr int ROWSTEP = 128 / KQ;
    constexpr int NAR = 64 / ROWSTEP;
    constexpr int NWR = KT / 4;

    float4 stA[NAR];
    float4 stW[NWR];
    const int arow = tid / KQ, akq = tid % KQ;

    auto loadRegs = [&](int k0) {
        #pragma unroll
        for (int r = 0; r < NAR; r++) {
            int row = arow + r * ROWSTEP;
            int kg = k0 + akq * 4;
            float4 v = make_float4(0.f, 0.f, 0.f, 0.f);
            if (kg < kend) v = *(const float4*)(A + (size_t)row * K + kg);
            stA[r] = v;
        }
        #pragma unroll
        for (int r = 0; r < NWR; r++) {
            int idx = tid + r * 128;
            int kk = idx >> 5, jq = idx & 31;
            int kg = k0 + kk, jg = jtile + jq * 4;
            float4 v = make_float4(0.f, 0.f, 0.f, 0.f);
            if (kg < kend) {
                if (VECW) {
                    if (jg < N) v = *(const float4*)(W + (size_t)kg * N + jg);
                } else {
                    const float* wr = W + (size_t)kg * N;
                    if (jg < N)     v.x = wr[jg];
                    if (jg + 1 < N) v.y = wr[jg + 1];
                    if (jg + 2 < N) v.z = wr[jg + 2];
                    if (jg + 3 < N) v.w = wr[jg + 3];
                }
            }
            stW[r] = v;
        }
    };
    auto storeSmem = [&](int buf) {
        #pragma unroll
        for (int r = 0; r < NAR; r++) {
            int row = arow + r * ROWSTEP;
            As[buf][akq * 4 + 0][row] = stA[r].x;
            As[buf][akq * 4 + 1][row] = stA[r].y;
            As[buf][akq * 4 + 2][row] = stA[r].z;
            As[buf][akq * 4 + 3][row] = stA[r].w;
        }
        #pragma unroll
        for (int r = 0; r < NWR; r++) {
            int idx = tid + r * 128;
            int kk = idx >> 5, jq = idx & 31;
            *(float4*)&Ws[buf][kk][jq * 4] = stW[r];
        }
    };

    ull acc[8][4] = {};

    loadRegs(kbeg);
    storeSmem(0);
    __syncthreads();

    for (int t = 0; t < nk; t++) {
        int cur = t & 1;
        if (t + 1 < nk) loadRegs(kbeg + (t + 1) * KT);
        #pragma unroll 8
        for (int kk = 0; kk < KT; kk++) {
            float4 aA = *(const float4*)&As[cur][kk][ty * 8];
            float4 aB = *(const float4*)&As[cur][kk][ty * 8 + 4];
            float4 b0 = *(const float4*)&Ws[cur][kk][tx * 8];
            float4 b1 = *(const float4*)&Ws[cur][kk][tx * 8 + 4];
            ull bp0 = ULO(b0), bp1 = UHI(b0), bp2 = ULO(b1), bp3 = UHI(b1);
            ull av;
            av = bcast2(aA.x); fma2(acc[0][0], av, bp0); fma2(acc[0][1], av, bp1); fma2(acc[0][2], av, bp2); fma2(acc[0][3], av, bp3);
            av = bcast2(aA.y); fma2(acc[1][0], av, bp0); fma2(acc[1][1], av, bp1); fma2(acc[1][2], av, bp2); fma2(acc[1][3], av, bp3);
            av = bcast2(aA.z); fma2(acc[2][0], av, bp0); fma2(acc[2][1], av, bp1); fma2(acc[2][2], av, bp2); fma2(acc[2][3], av, bp3);
            av = bcast2(aA.w); fma2(acc[3][0], av, bp0); fma2(acc[3][1], av, bp1); fma2(acc[3][2], av, bp2); fma2(acc[3][3], av, bp3);
            av = bcast2(aB.x); fma2(acc[4][0], av, bp0); fma2(acc[4][1], av, bp1); fma2(acc[4][2], av, bp2); fma2(acc[4][3], av, bp3);
            av = bcast2(aB.y); fma2(acc[5][0], av, bp0); fma2(acc[5][1], av, bp1); fma2(acc[5][2], av, bp2); fma2(acc[5][3], av, bp3);
            av = bcast2(aB.z); fma2(acc[6][0], av, bp0); fma2(acc[6][1], av, bp1); fma2(acc[6][2], av, bp2); fma2(acc[6][3], av, bp3);
            av = bcast2(aB.w); fma2(acc[7][0], av, bp0); fma2(acc[7][1], av, bp1); fma2(acc[7][2], av, bp2); fma2(acc[7][3], av, bp3);
        }
        if (t + 1 < nk) storeSmem(cur ^ 1);
        __syncthreads();
    }

    float* p = part + (size_t)sidx * ((size_t)Bz * Np);
    int j0 = jtile + tx * 8;
    #pragma unroll
    for (int i = 0; i < 8; i++) {
        int b = ty * 8 + i;
        float2 p0 = u2f(acc[i][0]), p1 = u2f(acc[i][1]), p2 = u2f(acc[i][2]), p3 = u2f(acc[i][3]);
        if (j0 + 4 <= Nck)
            *(float4*)(p + (size_t)b * Np + j0) = make_float4(p0.x, p0.y, p1.x, p1.y);
        if (j0 + 8 <= Nck)
            *(float4*)(p + (size_t)b * Np + j0 + 4) = make_float4(p2.x, p2.y, p3.x, p3.y);
    }
}

template<int KT, bool VECW>
__global__ void __launch_bounds__(128)
gemm64w(const float* __restrict__ A, const float* __restrict__ W,
        float* __restrict__ part, int K, int N, int Nck, int Np, int Kc, int split_base)
{
    int kbeg = blockIdx.y * Kc;
    gemm_body<KT, VECW>(A, W, part, K, N, Nck, Np, kbeg, min(kbeg + Kc, K),
                        blockIdx.x * 128, split_base + blockIdx.y);
}

// dual GEMM: blocks [0,nblk1) -> GEMM1, rest -> GEMM2 (both KT=16, VECW)
__global__ void __launch_bounds__(128)
gemm64w_dual(const float* __restrict__ A1, const float* __restrict__ W1,
             int K1, int N1, int Np1, int Kc1, int sb1, int nx1, int nblk1,
             const float* __restrict__ A2, const float* __restrict__ W2,
             int K2, int N2, int Np2, int Kc2, int sb2, int nx2,
             float* __restrict__ part)
{
    int f = blockIdx.x;
    const float* A; const float* W;
    int K, N, Np, Kc, sb, jt, ks;
    if (f < nblk1) {
        A = A1; W = W1; K = K1; N = N1; Np = Np1; Kc = Kc1; sb = sb1;
        jt = f % nx1; ks = f / nx1;
    } else {
        f -= nblk1;
        A = A2; W = W2; K = K2; N = N2; Np = Np2; Kc = Kc2; sb = sb2;
        jt = f % nx2; ks = f / nx2;
    }
    int kbeg = ks * Kc;
    gemm_body<16, true>(A, W, part, K, N, N, Np, kbeg, min(kbeg + Kc, K), jt * 128, sb + ks);
}

// combine: out4[i] = act( sum_s part4[s][i] ) — 4-way unrolled split loop (MLP=4)
__global__ void k_combine(const float* __restrict__ part, float* __restrict__ out,
                          int count4, int S, int stride4, int act)
{
    int idx = blockIdx.x * 256 + threadIdx.x;
    if (idx >= count4) return;
    const float4* p4 = (const float4*)part + idx;
    float4 s0 = make_float4(0.f, 0.f, 0.f, 0.f);
    float4 s1 = s0, s2 = s0, s3 = s0;
    int ss = 0;
    for (; ss + 4 <= S; ss += 4) {
        float4 a = p4[(size_t)(ss + 0) * stride4];
        float4 b = p4[(size_t)(ss + 1) * stride4];
        float4 c = p4[(size_t)(ss + 2) * stride4];
        float4 d = p4[(size_t)(ss + 3) * stride4];
        s0 = f4add(s0, a); s1 = f4add(s1, b); s2 = f4add(s2, c); s3 = f4add(s3, d);
    }
    for (; ss < S; ss++) s0 = f4add(s0, p4[(size_t)ss * stride4]);
    float4 s = f4add(f4add(s0, s1), f4add(s2, s3));
    if (act) { s.x = tanhf(s.x); s.y = tanhf(s.y); s.z = tanhf(s.z); s.w = tanhf(s.w); }
    ((float4*)out)[idx] = s;
}

// combine gates partials (two split ranges) + bias + LSTM cell
__global__ void k_combine_cell(const float* __restrict__ part, const float* __restrict__ bias,
                               const float* __restrict__ c0,
                               float* __restrict__ h1, float* __restrict__ c1,
                               int S1, int base2, int S2)
{
    int idx = blockIdx.x * 256 + threadIdx.x;
    if (idx >= Bz * Hh / 4) return;
    int b = idx >> 7, hq = idx & 127;
    const float4* p4 = (const float4*)part;
    const float4* b4 = (const float4*)bias;
    float4 g0 = b4[hq], g1 = b4[128 + hq], g2 = b4[256 + hq], g3 = b4[384 + hq];
    for (int ss = 0; ss < S1; ss++) {
        const float4* pb = p4 + (size_t)(ss * Bz + b) * 512;
        g0 = f4add(g0, pb[hq]);
        g1 = f4add(g1, pb[128 + hq]);
        g2 = f4add(g2, pb[256 + hq]);
        g3 = f4add(g3, pb[384 + hq]);
    }
    for (int ss = base2; ss < base2 + S2; ss++) {
        const float4* pb = p4 + (size_t)(ss * Bz + b) * 512;
        g0 = f4add(g0, pb[hq]);
        g1 = f4add(g1, pb[128 + hq]);
        g2 = f4add(g2, pb[256 + hq]);
        g3 = f4add(g3, pb[384 + hq]);
    }
    float4 c0v = ((const float4*)c0)[idx];
    float4 cc, hh;
    { float ig = sigmoidf(g0.x), fg = sigmoidf(g1.x), gg = tanhf(g2.x), og = sigmoidf(g3.x);
      cc.x = fg * c0v.x + ig * gg; hh.x = og * tanhf(cc.x); }
    { float ig = sigmoidf(g0.y), fg = sigmoidf(g1.y), gg = tanhf(g2.y), og = sigmoidf(g3.y);
      cc.y = fg * c0v.y + ig * gg; hh.y = og * tanhf(cc.y); }
    { float ig = sigmoidf(g0.z), fg = sigmoidf(g1.z), gg = tanhf(g2.z), og = sigmoidf(g3.z);
      cc.z = fg * c0v.z + ig * gg; hh.z = og * tanhf(cc.z); }
    { float ig = sigmoidf(g0.w), fg = sigmoidf(g1.w), gg = tanhf(g2.w), og = sigmoidf(g3.w);
      cc.w = fg * c0v.w + ig * gg; hh.w = og * tanhf(cc.w); }
    ((float4*)c1)[idx] = cc;
    ((float4*)h1)[idx] = hh;
}

// ---------------- K_select (mode1: ctx side) ----------------
__global__ void k_select(const float* __restrict__ weights, const float* __restrict__ lmask,
                         const float* __restrict__ land, int* __restrict__ out_idx,
                         float* __restrict__ out_rows, float* __restrict__ out_norm,
                         const float* __restrict__ lrel_src, const float* __restrict__ rmask_src,
                         float* __restrict__ out_lrel, float* __restrict__ out_rmask, int mode)
{
    int b = blockIdx.x;
    int t = threadIdx.x;  // 128
    __shared__ float v[Mm];
    __shared__ int bidx[TOPN];
    __shared__ float red[128];

    v[t] = weights[b * CFG + (t >> 3)] * lmask[b * Mm + t];
    __syncthreads();
    if (t == 0) {
        for (int rep = 0; rep < TOPN; rep++) {
            float bv = v[0]; int bi = 0;
            for (int m = 1; m < Mm; m++) { float x = v[m]; if (x > bv) { bv = x; bi = m; } }
            bidx[rep] = bi; v[bi] = -3.4e38f;
        }
    }
    __syncthreads();
    if (t < TOPN) out_idx[b * TOPN + t] = bidx[t];

    for (int tt = 0; tt < TOPN; tt++) {
        int m = bidx[tt];
        const float4* src = (const float4*)(land + ((size_t)(b * Mm + m)) * Dd);
        float4* dst = (float4*)(out_rows + ((size_t)(b * TOPN + tt)) * Dd);
        float part = 0.f;
        for (int j = t; j < D4; j += 128) {
            float4 x = src[j];
            dst[j] = x;
            part += dot4(x, x);
        }
        red[t] = part; __syncthreads();
        for (int off = 64; off > 0; off >>= 1) { if (t < off) red[t] += red[t + off]; __syncthreads(); }
        if (t == 0) out_norm[b * TOPN + tt] = sqrtf(red[0]);
        __syncthreads();
    }

    if (mode == 1) {
        if (t < TOPN * 6) {
            int tt = t / 6, r = t % 6;
            out_lrel[(b * TOPN + tt) * 6 + r] = lrel_src[((size_t)(b * Mm + bidx[tt])) * 6 + r];
        }
        if (t < TOPN) out_rmask[b * TOPN + t] = rmask_src[b * Mm + bidx[t]];
    }
}

// ---------------- K_select_act: blocks [0,Bz)=select(mode0); [Bz,2Bz)=actemb ----------------
__global__ void k_select_act(const float* __restrict__ weights, const float* __restrict__ lmask,
                             const float* __restrict__ land, int* __restrict__ out_idx,
                             float* __restrict__ out_rows, float* __restrict__ out_norm,
                             const float* __restrict__ action, const float* __restrict__ embW,
                             const float* __restrict__ embb, float* __restrict__ x)
{
    int t = threadIdx.x;  // 128
    if (blockIdx.x >= Bz) {
        int b = blockIdx.x - Bz;
        if (t < EMB) {
            float acc = 0.f;
            #pragma unroll 4
            for (int a = 0; a < ANG; a++) acc += action[b * ANG + a] * embW[a * EMB + t];
            x[(size_t)b * XDIM + t] = tanhf(acc + embb[t]);
        }
        return;
    }
    int b = blockIdx.x;
    __shared__ float v[Mm];
    __shared__ int bidx[TOPN];
    __shared__ float red[128];

    v[t] = weights[b * CFG + (t >> 3)] * lmask[b * Mm + t];
    __syncthreads();
    if (t == 0) {
        for (int rep = 0; rep < TOPN; rep++) {
            float bv = v[0]; int bi = 0;
            for (int m = 1; m < Mm; m++) { float xx = v[m]; if (xx > bv) { bv = xx; bi = m; } }
            bidx[rep] = bi; v[bi] = -3.4e38f;
        }
    }
    __syncthreads();
    if (t < TOPN) out_idx[b * TOPN + t] = bidx[t];

    for (int tt = 0; tt < TOPN; tt++) {
        int m = bidx[tt];
        const float4* src = (const float4*)(land + ((size_t)(b * Mm + m)) * Dd);
        float4* dst = (float4*)(out_rows + ((size_t)(b * TOPN + tt)) * Dd);
        float part = 0.f;
        for (int j = t; j < D4; j += 128) {
            float4 xx = src[j];
            dst[j] = xx;
            part += dot4(xx, xx);
        }
        red[t] = part; __syncthreads();
        for (int off = 64; off > 0; off >>= 1) { if (t < off) red[t] += red[t + off]; __syncthreads(); }
        if (t == 0) out_norm[b * TOPN + tt] = sqrtf(red[0]);
        __syncthreads();
    }
}

// ---------------- K_pano ----------------
__global__ void k_pano(const float* __restrict__ pano_obj, const float* __restrict__ land_sel,
                       const float* __restrict__ land_norm, float* __restrict__ pano_sim)
{
    int b = blockIdx.y, p = blockIdx.x;
    int tid = threadIdx.x;              // 256
    int warp = tid >> 5, lane = tid & 31;
    __shared__ float4 land4[TOPN * D4];
    __shared__ float lnorm[TOPN];
    __shared__ float sim[OBJ][TOPN];
    __shared__ int best[TOPN];

    const float4* ls4 = (const float4*)(land_sel + (size_t)b * TOPN * Dd);
    for (int idx = tid; idx < TOPN * D4; idx += 256) land4[idx] = ls4[idx];
    if (tid < TOPN) lnorm[tid] = land_norm[b * TOPN + tid];
    __syncthreads();

    const float* obase = pano_obj + ((size_t)(b * PANO + p)) * OBJ * Dd;
    for (int o = warp; o < OBJ; o += 8) {
        const float4* row4 = (const float4*)(obase + (size_t)o * Dd);
        float a0 = 0, a1 = 0, a2 = 0, an = 0;
        for (int j = lane; j < D4; j += 32) {
            float4 f = row4[j];
            a0 += dot4(f, land4[j]);
            a1 += dot4(f, land4[D4 + j]);
            a2 += dot4(f, land4[2 * D4 + j]);
            an += dot4(f, f);
        }
        a0 = warp_sum(a0); a1 = warp_sum(a1); a2 = warp_sum(a2); an = warp_sum(an);
        if (lane == 0) {
            float no = sqrtf(an);
            sim[o][0] = a0 / fmaxf(no * lnorm[0], EPSV);
            sim[o][1] = a1 / fmaxf(no * lnorm[1], EPSV);
            sim[o][2] = a2 / fmaxf(no * lnorm[2], EPSV);
        }
    }
    __syncthreads();
    if (tid < TOPN) {
        float bv = sim[0][tid]; int bi = 0;
        for (int o = 1; o < OBJ; o++) { float s = sim[o][tid]; if (s > bv) { bv = s; bi = o; } }
        best[tid] = bi;
    }
    __syncthreads();
    float4* dst = (float4*)(pano_sim + ((size_t)(b * PANO + p)) * TOPN * Dd);
    for (int idx = tid; idx < TOPN * D4; idx += 256) {
        int tt = idx / D4, j = idx % D4;
        dst[idx] = ((const float4*)(obase + (size_t)best[tt] * Dd))[j];
    }
}

// ---------------- K_attn_logits: one (b,s) dot per block ----------------
__global__ void k_attn_logits(const float* __restrict__ feature, const float* __restrict__ pano_sim,
                              const float* __restrict__ qf, float* __restrict__ aval)
{
    int s = blockIdx.x, b = blockIdx.y;
    int tid = threadIdx.x; // 256
    __shared__ float red[256];
    const float4* f4  = (const float4*)(feature + ((size_t)(b * PANO + s)) * FEAT);
    const float4* ps4 = (const float4*)(pano_sim + ((size_t)(b * PANO + s)) * TOPN * Dd);
    const float4* q4  = (const float4*)(qf + (size_t)b * FEAT_ALL);
    float acc = 0.f;
    for (int j = tid; j < F4F; j += 256) acc += dot4(f4[j], q4[j]);
    for (int j = tid; j < F4P; j += 256) acc += dot4(ps4[j], q4[F4F + j]);
    red[tid] = acc; __syncthreads();
    for (int off = 128; off > 0; off >>= 1) { if (tid < off) red[tid] += red[tid + off]; __syncthreads(); }
    if (tid == 0) aval[b * PANO + s] = red[0];
}

// ---------------- K_attn_feat: fused softmax(aval) + weighted sum ----------------
__global__ void k_attn_feat(const float* __restrict__ feature, const float* __restrict__ pano_sim,
                            const float* __restrict__ aval, float* __restrict__ x)
{
    int b = blockIdx.y;
    int j = blockIdx.x * 128 + threadIdx.x;
    __shared__ float p[PANO];
    if (threadIdx.x < PANO) p[threadIdx.x] = aval[b * PANO + threadIdx.x];
    __syncthreads();
    if (threadIdx.x == 0) {
        float mx = p[0];
        for (int s = 1; s < PANO; s++) mx = fmaxf(mx, p[s]);
        float sum = 0.f;
        for (int s = 0; s < PANO; s++) { float e = expf(p[s] - mx); p[s] = e; sum += e; }
        float inv = 1.0f / sum;
        for (int s = 0; s < PANO; s++) p[s] *= inv;
    }
    __syncthreads();
    if (j >= F4A) return;
    float4 acc = make_float4(0.f, 0.f, 0.f, 0.f);
    if (j < F4F) {
        const float4* f4 = (const float4*)(feature + (size_t)b * PANO * FEAT) + j;
        #pragma unroll 4
        for (int s = 0; s < PANO; s++) {
            float4 v = f4[(size_t)s * F4F];
            float w = p[s];
            acc.x += w * v.x; acc.y += w * v.y; acc.z += w * v.z; acc.w += w * v.w;
        }
    } else {
        const float4* f4 = (const float4*)(pano_sim + (size_t)b * PANO * TOPN * Dd) + (j - F4F);
        #pragma unroll 4
        for (int s = 0; s < PANO; s++) {
            float4 v = f4[(size_t)s * F4P];
            float w = p[s];
            acc.x += w * v.x; acc.y += w * v.y; acc.z += w * v.z; acc.w += w * v.w;
        }
    }
    ((float4*)(x + (size_t)b * XDIM + EMB))[j] = acc;
}

// ---------------- K_ctx ----------------
__global__ void k_ctx(const float* __restrict__ ctx, const float* __restrict__ part,
                      const float* __restrict__ h1, float* __restrict__ ctx_attn,
                      float* __restrict__ cat, int S)
{
    int b = blockIdx.x;
    int tid = threadIdx.x, warp = tid >> 5, lane = tid & 31; // 512 threads
    __shared__ float4 q2s[128];
    __shared__ float lg[CFG];
    __shared__ float pr[CFG];

    if (tid < 128) {
        const float4* p4 = (const float4*)part;
        float4 s = make_float4(0.f, 0.f, 0.f, 0.f);
        for (int ss = 0; ss < S; ss++)
            s = f4add(s, p4[(size_t)(ss * Bz + b) * 128 + tid]);
        q2s[tid] = s;
    }
    __syncthreads();
    {
        int s = warp;
        const float4* c4 = (const float4*)(ctx + ((size_t)(b * CFG + s)) * Hh);
        float acc = 0.f;
        for (int j = lane; j < 128; j += 32) acc += dot4(c4[j], q2s[j]);
        acc = warp_sum(acc);
        if (lane == 0) lg[s] = acc;
    }
    __syncthreads();
    if (tid == 0) {
        float mx = lg[0];
        for (int s = 1; s < CFG; s++) mx = fmaxf(mx, lg[s]);
        float sum = 0.f;
        for (int s = 0; s < CFG; s++) { float e = expf(lg[s] - mx); pr[s] = e; sum += e; }
        float inv = 1.0f / sum;
        for (int s = 0; s < CFG; s++) pr[s] *= inv;
    }
    __syncthreads();
    if (tid < CFG) ctx_attn[b * CFG + tid] = pr[tid];
    if (tid < 128) {
        const float4* c4 = (const float4*)(ctx + (size_t)b * CFG * Hh) + tid;
        float4 acc = make_float4(0.f, 0.f, 0.f, 0.f);
        #pragma unroll
        for (int s = 0; s < CFG; s++) {
            float4 v = c4[(size_t)s * 128];
            float w = pr[s];
            acc.x += w * v.x; acc.y += w * v.y; acc.z += w * v.z; acc.w += w * v.w;
        }
        ((float4*)(cat + (size_t)b * 2 * Hh))[tid] = acc;
        ((float4*)(cat + (size_t)b * 2 * Hh + Hh))[tid] = ((const float4*)(h1 + (size_t)b * Hh))[tid];
    }
}

// ---------------- K_logit ----------------
__global__ void k_logit(const float* __restrict__ cand_obj, const float* __restrict__ cland,
                        const float* __restrict__ cland_norm, const float* __restrict__ cand_feat,
                        const float* __restrict__ crel_in, const float* __restrict__ lrel,
                        const float* __restrict__ rmask, const float* __restrict__ q3,
                        float* __restrict__ logit)
{
    int b = blockIdx.y, i = blockIdx.x;
    int tid = threadIdx.x, warp = tid >> 5, lane = tid & 31; // 256
    __shared__ float4 land4[TOPN * D4];
    __shared__ float lnorm[TOPN];
    __shared__ float sim[OBJ][TOPN];
    __shared__ int best[TOPN];
    __shared__ float red[256];

    const float4* ls4 = (const float4*)(cland + (size_t)b * TOPN * Dd);
    for (int idx = tid; idx < TOPN * D4; idx += 256) land4[idx] = ls4[idx];
    if (tid < TOPN) lnorm[tid] = cland_norm[b * TOPN + tid];
    __syncthreads();

    const float* obase = cand_obj + ((size_t)(b * IMG + i)) * OBJ * Dd;
    for (int o = warp; o < OBJ; o += 8) {
        const float4* row4 = (const float4*)(obase + (size_t)o * Dd);
        float a0 = 0, a1 = 0, a2 = 0, an = 0;
        for (int j = lane; j < D4; j += 32) {
            float4 f = row4[j];
            a0 += dot4(f, land4[j]);
            a1 += dot4(f, land4[D4 + j]);
            a2 += dot4(f, land4[2 * D4 + j]);
            an += dot4(f, f);
        }
        a0 = warp_sum(a0); a1 = warp_sum(a1); a2 = warp_sum(a2); an = warp_sum(an);
        if (lane == 0) {
            float no = sqrtf(an);
            sim[o][0] = a0 / fmaxf(no * lnorm[0], EPSV);
            sim[o][1] = a1 / fmaxf(no * lnorm[1], EPSV);
            sim[o][2] = a2 / fmaxf(no * lnorm[2], EPSV);
        }
    }
    __syncthreads();
    if (tid < TOPN) {
        float bv = sim[0][tid]; int bi = 0;
        for (int o = 1; o < OBJ; o++) { float s = sim[o][tid]; if (s > bv) { bv = s; bi = o; } }
        best[tid] = bi;
    }
    __syncthreads();

    const float* q = q3 + (size_t)b * CAND_PAD;
    const float4* q4 = (const float4*)q;
    const float4* cf4 = (const float4*)(cand_feat + ((size_t)(b * IMG + i)) * FEAT);
    float part = 0.f;
    for (int j = tid; j < F4F; j += 256) part += dot4(cf4[j], q4[j]);
    for (int idx = tid; idx < TOPN * D4; idx += 256) {
        int tt = idx / D4, j = idx % D4;
        float4 f = ((const float4*)(obase + (size_t)best[tt] * Dd))[j];
        const float* qs = q + FEAT + tt * (Dd + 7) + j * 4;
        part += f.x * qs[0] + f.y * qs[1] + f.z * qs[2] + f.w * qs[3];
    }
    red[tid] = part; __syncthreads();
    for (int off = 128; off > 0; off >>= 1) { if (tid < off) red[tid] += red[tid + off]; __syncthreads(); }
    if (tid == 0) {
        float s = red[0];
        const float* cr = crel_in + ((size_t)(b * IMG + i)) * 6;
        for (int tt = 0; tt < TOPN; tt++) {
            const float* qs = q + FEAT + tt * (Dd + 7);
            float rm = rmask[b * TOPN + tt];
            float lor = 0.f;
            #pragma unroll
            for (int r = 0; r < 6; r++) {
                lor += cr[r] * lrel[(b * TOPN + tt) * 6 + r];
                s += cr[r] * rm * qs[Dd + r];
            }
            s += lor * qs[Dd + 6];
        }
        logit[b * IMG + i] = s;
    }
}

// ---------------- launch (single stream) ----------------
extern "C" void kernel_launch(void* const* d_in, const int* in_sizes, int n_in,
                              void* d_out, int out_size)
{
    const float* action     = (const float*)d_in[0];
    const float* feature    = (const float*)d_in[1];
    const float* cand_feat  = (const float*)d_in[2];
    const float* prev_h1    = (const float*)d_in[3];
    const float* c_0        = (const float*)d_in[4];
    const float* ctx        = (const float*)d_in[5];
    const float* s_0        = (const float*)d_in[6];
    const float* land       = (const float*)d_in[7];
    const float* cand_obj   = (const float*)d_in[8];
    const float* lmask      = (const float*)d_in[9];
    const float* lrel_in    = (const float*)d_in[10];
    const float* rmask_in   = (const float*)d_in[11];
    const float* crel_in    = (const float*)d_in[12];
    const float* pano_obj   = (const float*)d_in[13];
    const float* embW       = (const float*)d_in[14];
    const float* embb       = (const float*)d_in[15];
    const float* W_ih       = (const float*)d_in[16];
    const float* W_hh       = (const float*)d_in[17];
    const float* b_lstm     = (const float*)d_in[18];
    const float* feat_in_W  = (const float*)d_in[19];
    const float* att_in_W   = (const float*)d_in[20];
    const float* att_out_W  = (const float*)d_in[21];
    const float* cand_in_W  = (const float*)d_in[22];

    float* out   = (float*)d_out;
    float* h1    = out;
    float* c1    = out + Bz * Hh;
    float* logit = out + 2 * Bz * Hh;
    float* ht    = out + 2 * Bz * Hh + Bz * IMG;
    float* ctxa  = ht + Bz * Hh;

    int   *p_top, *p_ctop;
    float *p_lsel, *p_lnorm, *p_cland, *p_clnorm, *p_lrel, *p_rmask, *p_psim;
    float *p_qf, *p_av, *p_x, *p_cat, *p_qc, *p_part;
    cudaGetSymbolAddress((void**)&p_top,    g_top_idx);
    cudaGetSymbolAddress((void**)&p_ctop,   g_ctop);
    cudaGetSymbolAddress((void**)&p_lsel,   g_land_sel);
    cudaGetSymbolAddress((void**)&p_lnorm,  g_land_norm);
    cudaGetSymbolAddress((void**)&p_cland,  g_cland);
    cudaGetSymbolAddress((void**)&p_clnorm, g_cland_norm);
    cudaGetSymbolAddress((void**)&p_lrel,   g_lrel);
    cudaGetSymbolAddress((void**)&p_rmask,  g_rmask);
    cudaGetSymbolAddress((void**)&p_psim,   g_pano_sim);
    cudaGetSymbolAddress((void**)&p_qf,     g_q_feat);
    cudaGetSymbolAddress((void**)&p_av,     g_aval);
    cudaGetSymbolAddress((void**)&p_x,      g_x);
    cudaGetSymbolAddress((void**)&p_cat,    g_cat);
    cudaGetSymbolAddress((void**)&p_qc,     g_q_cand);
    cudaGetSymbolAddress((void**)&p_part,   g_part);

    // 1. top-3 landmark selection from s_0 + action embedding (merged launch)
    k_select_act<<<2 * Bz, 128>>>(s_0, lmask, land, p_top, p_lsel, p_lnorm,
                                  action, embW, embb, p_x);
    // 2. pano cosine argmax + gather
    k_pano<<<dim3(PANO, Bz), 256>>>(pano_obj, p_lsel, p_lnorm, p_psim);
    // 3. dual GEMM: q_feat (splits 0..15, Np=FEAT_ALL) + W_hh (splits 25..40, Np=G4)
    gemm64w_dual<<<656, 128>>>(prev_h1, feat_in_W, Hh, FEAT_ALL, FEAT_ALL, 32, 0, 25, 400,
                               prev_h1, W_hh, Hh, G4, G4, 32, 25, 16, p_part);
    k_combine<<<(Bz * F4A + 255) / 256, 256>>>(p_part, p_qf, Bz * F4A, 16, Bz * F4A, 0);
    // 4. attention logits (full-chip parallel); softmax fused into attn_feat
    k_attn_logits<<<dim3(PANO, Bz), 256>>>(feature, p_psim, p_qf, p_av);
    // 5. attn_feat (fused softmax) -> x[:, 64:]
    k_attn_feat<<<dim3((F4A + 127) / 128, Bz), 128>>>(feature, p_psim, p_av, p_x);
    // 6. W_ih GEMM (KT=32, splits 0..19, Kc=160 nk=5), then fused cell over two split ranges
    gemm64w<32, true><<<dim3(16, 20), 128>>>(p_x, W_ih, p_part, XDIM, G4, G4, G4, 160, 0);
    k_combine_cell<<<(Bz * Hh / 4 + 255) / 256, 256>>>(p_part, b_lstm, c_0, h1, c1, 20, 25, 16);
    // 7. q2 partials (KT=16, S=16) + ctx attention (fused combine)
    gemm64w<16, true><<<dim3(4, 16), 128>>>(h1, att_in_W, p_part, Hh, Hh, Hh, Hh, 32, 0);
    k_ctx<<<Bz, 512>>>(ctx, p_part, h1, ctxa, p_cat, 16);
    // 8. h_tilde = tanh([wctx,h1] @ att_out_W)  (KT=32, S=16, Kc=64 nk=2)
    gemm64w<32, true><<<dim3(4, 16), 128>>>(p_cat, att_out_W, p_part, 2 * Hh, Hh, Hh, Hh, 64, 0);
    k_combine<<<(Bz * Hh / 4 + 255) / 256, 256>>>(p_part, ht, Bz * Hh / 4, 16, Bz * Hh / 4, 1);
    // 9. top-3 from ctx_attn + relation gathers
    k_select<<<Bz, 128>>>(ctxa, lmask, land, p_ctop, p_cland, p_clnorm,
                          lrel_in, rmask_in, p_lrel, p_rmask, 1);
    // 10. q3 (KT=16, S=16; N=3097 odd -> scalar W loads)
    gemm64w<16, false><<<dim3(25, 16), 128>>>(ht, cand_in_W, p_part, Hh, CAND_ALL, 3100, CAND_PAD, 32, 0);
    k_combine<<<(Bz * CAND_PAD / 4 + 255) / 256, 256>>>(p_part, p_qc, Bz * CAND_PAD / 4, 16, Bz * CAND_PAD / 4, 0);
    // 11. candidate argmax + logits
    k_logit<<<dim3(IMG, Bz), 256>>>(cand_obj, p_cland, p_clnorm, cand_feat,
                                    crel_in, p_lrel, p_rmask, p_qc, logit);
}

// round 16
// speedup vs baseline: 1.0078x; 1.0078x over previous
#include <cuda_runtime.h>
#include <math.h>

// ---------------- problem constants ----------------
#define Bz   64
#define PANO 36
#define OBJ  36
#define CFG  16
#define LM   8
#define IMG  32
#define Dd   300
#define Hh   512
#define EMB  64
#define ANG  128
#define FEAT 2176
#define TOPN 3
#define Mm   128
#define FEAT_ALL 3076     // FEAT + TOPN*D
#define XDIM 3140         // EMB + FEAT_ALL
#define G4   2048         // 4*H
#define CAND_ALL 3097     // FEAT + TOPN*7 + TOPN*D
#define CAND_PAD 3104     // padded to /4
#define EPSV 1e-8f

#define F4A  769          // FEAT_ALL/4
#define F4F  544          // FEAT/4
#define F4P  225          // TOPN*Dd/4
#define D4   75           // Dd/4

typedef unsigned long long ull;

// ---------------- scratch ----------------
__device__ int   g_top_idx[Bz * TOPN];
__device__ int   g_ctop[Bz * TOPN];
__device__ float g_land_sel[Bz * TOPN * Dd];
__device__ float g_land_norm[Bz * TOPN];
__device__ float g_cland[Bz * TOPN * Dd];
__device__ float g_cland_norm[Bz * TOPN];
__device__ float g_lrel[Bz * TOPN * 6];
__device__ float g_rmask[Bz * TOPN];
__device__ float g_pano_sim[(size_t)Bz * PANO * TOPN * Dd];
__device__ float g_q_feat[Bz * FEAT_ALL];
__device__ float g_aval[Bz * PANO];
__device__ float g_x[Bz * XDIM];
__device__ float g_cat[Bz * 2 * Hh];
__device__ float g_q_cand[Bz * CAND_PAD];
__device__ float g_part[5505024];   // split-K partials

// ---------------- helpers ----------------
__device__ __forceinline__ float warp_sum(float v) {
    #pragma unroll
    for (int off = 16; off > 0; off >>= 1) v += __shfl_xor_sync(0xffffffffu, v, off);
    return v;
}
__device__ __forceinline__ float sigmoidf(float x) { return 1.0f / (1.0f + expf(-x)); }
__device__ __forceinline__ float dot4(float4 a, float4 b) {
    return a.x * b.x + a.y * b.y + a.z * b.z + a.w * b.w;
}
__device__ __forceinline__ float4 f4add(float4 a, float4 b) {
    return make_float4(a.x + b.x, a.y + b.y, a.z + b.z, a.w + b.w);
}
// ---- packed f32x2 (sm_103a FFMA2) ----
__device__ __forceinline__ ull bcast2(float v) {
    ull r;
    asm("mov.b64 %0, {%1, %1};" : "=l"(r) : "f"(v));
    return r;
}
__device__ __forceinline__ void fma2(ull& acc, ull a, ull b) {
    asm("fma.rn.f32x2 %0, %1, %2, %0;" : "+l"(acc) : "l"(a), "l"(b));
}
__device__ __forceinline__ float2 u2f(ull u) {
    float2 f;
    asm("mov.b64 {%0, %1}, %2;" : "=f"(f.x), "=f"(f.y) : "l"(u));
    return f;
}
#define ULO(v4) (*(const ull*)&(v4).x)
#define UHI(v4) (*(const ull*)&(v4).z)

// ================= GEMM body (shared by single & dual wrappers) =================
#define ASTRIDE 72
template<int KT, bool VECW>
__device__ __forceinline__ void gemm_body(
    const float* __restrict__ A, const float* __restrict__ W, float* __restrict__ part,
    int K, int N, int Nck, int Np, int kbeg, int kend, int jtile, int sidx)
{
    __shared__ float As[2][KT][ASTRIDE];
    __shared__ float Ws[2][KT][128];
    const int tid = threadIdx.x;
    const int tx = tid & 15, ty = tid >> 4;
    const int nk = (kend - kbeg + KT - 1) / KT;

    constexpr int KQ = KT / 4;
    constexpr int ROWSTEP = 128 / KQ;
    constexpr int NAR = 64 / ROWSTEP;
    constexpr int NWR = KT / 4;

    float4 stA[NAR];
    float4 stW[NWR];
    const int arow = tid / KQ, akq = tid % KQ;

    auto loadRegs = [&](int k0) {
        #pragma unroll
        for (int r = 0; r < NAR; r++) {
            int row = arow + r * ROWSTEP;
            int kg = k0 + akq * 4;
            float4 v = make_float4(0.f, 0.f, 0.f, 0.f);
            if (kg < kend) v = *(const float4*)(A + (size_t)row * K + kg);
            stA[r] = v;
        }
        #pragma unroll
        for (int r = 0; r < NWR; r++) {
            int idx = tid + r * 128;
            int kk = idx >> 5, jq = idx & 31;
            int kg = k0 + kk, jg = jtile + jq * 4;
            float4 v = make_float4(0.f, 0.f, 0.f, 0.f);
            if (kg < kend) {
                if (VECW) {
                    if (jg < N) v = *(const float4*)(W + (size_t)kg * N + jg);
                } else {
                    const float* wr = W + (size_t)kg * N;
                    if (jg < N)     v.x = wr[jg];
                    if (jg + 1 < N) v.y = wr[jg + 1];
                    if (jg + 2 < N) v.z = wr[jg + 2];
                    if (jg + 3 < N) v.w = wr[jg + 3];
                }
            }
            stW[r] = v;
        }
    };
    auto storeSmem = [&](int buf) {
        #pragma unroll
        for (int r = 0; r < NAR; r++) {
            int row = arow + r * ROWSTEP;
            As[buf][akq * 4 + 0][row] = stA[r].x;
            As[buf][akq * 4 + 1][row] = stA[r].y;
            As[buf][akq * 4 + 2][row] = stA[r].z;
            As[buf][akq * 4 + 3][row] = stA[r].w;
        }
        #pragma unroll
        for (int r = 0; r < NWR; r++) {
            int idx = tid + r * 128;
            int kk = idx >> 5, jq = idx & 31;
            *(float4*)&Ws[buf][kk][jq * 4] = stW[r];
        }
    };

    ull acc[8][4] = {};

    loadRegs(kbeg);
    storeSmem(0);
    __syncthreads();

    for (int t = 0; t < nk; t++) {
        int cur = t & 1;
        if (t + 1 < nk) loadRegs(kbeg + (t + 1) * KT);
        #pragma unroll 8
        for (int kk = 0; kk < KT; kk++) {
            float4 aA = *(const float4*)&As[cur][kk][ty * 8];
            float4 aB = *(const float4*)&As[cur][kk][ty * 8 + 4];
            float4 b0 = *(const float4*)&Ws[cur][kk][tx * 8];
            float4 b1 = *(const float4*)&Ws[cur][kk][tx * 8 + 4];
            ull bp0 = ULO(b0), bp1 = UHI(b0), bp2 = ULO(b1), bp3 = UHI(b1);
            ull av;
            av = bcast2(aA.x); fma2(acc[0][0], av, bp0); fma2(acc[0][1], av, bp1); fma2(acc[0][2], av, bp2); fma2(acc[0][3], av, bp3);
            av = bcast2(aA.y); fma2(acc[1][0], av, bp0); fma2(acc[1][1], av, bp1); fma2(acc[1][2], av, bp2); fma2(acc[1][3], av, bp3);
            av = bcast2(aA.z); fma2(acc[2][0], av, bp0); fma2(acc[2][1], av, bp1); fma2(acc[2][2], av, bp2); fma2(acc[2][3], av, bp3);
            av = bcast2(aA.w); fma2(acc[3][0], av, bp0); fma2(acc[3][1], av, bp1); fma2(acc[3][2], av, bp2); fma2(acc[3][3], av, bp3);
            av = bcast2(aB.x); fma2(acc[4][0], av, bp0); fma2(acc[4][1], av, bp1); fma2(acc[4][2], av, bp2); fma2(acc[4][3], av, bp3);
            av = bcast2(aB.y); fma2(acc[5][0], av, bp0); fma2(acc[5][1], av, bp1); fma2(acc[5][2], av, bp2); fma2(acc[5][3], av, bp3);
            av = bcast2(aB.z); fma2(acc[6][0], av, bp0); fma2(acc[6][1], av, bp1); fma2(acc[6][2], av, bp2); fma2(acc[6][3], av, bp3);
            av = bcast2(aB.w); fma2(acc[7][0], av, bp0); fma2(acc[7][1], av, bp1); fma2(acc[7][2], av, bp2); fma2(acc[7][3], av, bp3);
        }
        if (t + 1 < nk) storeSmem(cur ^ 1);
        __syncthreads();
    }

    float* p = part + (size_t)sidx * ((size_t)Bz * Np);
    int j0 = jtile + tx * 8;
    #pragma unroll
    for (int i = 0; i < 8; i++) {
        int b = ty * 8 + i;
        float2 p0 = u2f(acc[i][0]), p1 = u2f(acc[i][1]), p2 = u2f(acc[i][2]), p3 = u2f(acc[i][3]);
        if (j0 + 4 <= Nck)
            *(float4*)(p + (size_t)b * Np + j0) = make_float4(p0.x, p0.y, p1.x, p1.y);
        if (j0 + 8 <= Nck)
            *(float4*)(p + (size_t)b * Np + j0 + 4) = make_float4(p2.x, p2.y, p3.x, p3.y);
    }
}

template<int KT, bool VECW>
__global__ void __launch_bounds__(128)
gemm64w(const float* __restrict__ A, const float* __restrict__ W,
        float* __restrict__ part, int K, int N, int Nck, int Np, int Kc, int split_base)
{
    int kbeg = blockIdx.y * Kc;
    gemm_body<KT, VECW>(A, W, part, K, N, Nck, Np, kbeg, min(kbeg + Kc, K),
                        blockIdx.x * 128, split_base + blockIdx.y);
}

// dual GEMM: blocks [0,nblk1) -> GEMM1, rest -> GEMM2 (both KT=16, VECW)
__global__ void __launch_bounds__(128)
gemm64w_dual(const float* __restrict__ A1, const float* __restrict__ W1,
             int K1, int N1, int Np1, int Kc1, int sb1, int nx1, int nblk1,
             const float* __restrict__ A2, const float* __restrict__ W2,
             int K2, int N2, int Np2, int Kc2, int sb2, int nx2,
             float* __restrict__ part)
{
    int f = blockIdx.x;
    const float* A; const float* W;
    int K, N, Np, Kc, sb, jt, ks;
    if (f < nblk1) {
        A = A1; W = W1; K = K1; N = N1; Np = Np1; Kc = Kc1; sb = sb1;
        jt = f % nx1; ks = f / nx1;
    } else {
        f -= nblk1;
        A = A2; W = W2; K = K2; N = N2; Np = Np2; Kc = Kc2; sb = sb2;
        jt = f % nx2; ks = f / nx2;
    }
    int kbeg = ks * Kc;
    gemm_body<16, true>(A, W, part, K, N, N, Np, kbeg, min(kbeg + Kc, K), jt * 128, sb + ks);
}

// combine: out4[i] = act( sum_s part4[s][i] ) — 4-way unrolled split loop
__global__ void k_combine(const float* __restrict__ part, float* __restrict__ out,
                          int count4, int S, int stride4, int act)
{
    int idx = blockIdx.x * 256 + threadIdx.x;
    if (idx >= count4) return;
    const float4* p4 = (const float4*)part + idx;
    float4 s0 = make_float4(0.f, 0.f, 0.f, 0.f);
    float4 s1 = s0, s2 = s0, s3 = s0;
    int ss = 0;
    for (; ss + 4 <= S; ss += 4) {
        float4 a = p4[(size_t)(ss + 0) * stride4];
        float4 b = p4[(size_t)(ss + 1) * stride4];
        float4 c = p4[(size_t)(ss + 2) * stride4];
        float4 d = p4[(size_t)(ss + 3) * stride4];
        s0 = f4add(s0, a); s1 = f4add(s1, b); s2 = f4add(s2, c); s3 = f4add(s3, d);
    }
    for (; ss < S; ss++) s0 = f4add(s0, p4[(size_t)ss * stride4]);
    float4 s = f4add(f4add(s0, s1), f4add(s2, s3));
    if (act) { s.x = tanhf(s.x); s.y = tanhf(s.y); s.z = tanhf(s.z); s.w = tanhf(s.w); }
    ((float4*)out)[idx] = s;
}

// combine gates partials (two split ranges) + bias + LSTM cell
__global__ void k_combine_cell(const float* __restrict__ part, const float* __restrict__ bias,
                               const float* __restrict__ c0,
                               float* __restrict__ h1, float* __restrict__ c1,
                               int S1, int base2, int S2)
{
    int idx = blockIdx.x * 256 + threadIdx.x;
    if (idx >= Bz * Hh / 4) return;
    int b = idx >> 7, hq = idx & 127;
    const float4* p4 = (const float4*)part;
    const float4* b4 = (const float4*)bias;
    float4 g0 = b4[hq], g1 = b4[128 + hq], g2 = b4[256 + hq], g3 = b4[384 + hq];
    for (int ss = 0; ss < S1; ss++) {
        const float4* pb = p4 + (size_t)(ss * Bz + b) * 512;
        g0 = f4add(g0, pb[hq]);
        g1 = f4add(g1, pb[128 + hq]);
        g2 = f4add(g2, pb[256 + hq]);
        g3 = f4add(g3, pb[384 + hq]);
    }
    for (int ss = base2; ss < base2 + S2; ss++) {
        const float4* pb = p4 + (size_t)(ss * Bz + b) * 512;
        g0 = f4add(g0, pb[hq]);
        g1 = f4add(g1, pb[128 + hq]);
        g2 = f4add(g2, pb[256 + hq]);
        g3 = f4add(g3, pb[384 + hq]);
    }
    float4 c0v = ((const float4*)c0)[idx];
    float4 cc, hh;
    { float ig = sigmoidf(g0.x), fg = sigmoidf(g1.x), gg = tanhf(g2.x), og = sigmoidf(g3.x);
      cc.x = fg * c0v.x + ig * gg; hh.x = og * tanhf(cc.x); }
    { float ig = sigmoidf(g0.y), fg = sigmoidf(g1.y), gg = tanhf(g2.y), og = sigmoidf(g3.y);
      cc.y = fg * c0v.y + ig * gg; hh.y = og * tanhf(cc.y); }
    { float ig = sigmoidf(g0.z), fg = sigmoidf(g1.z), gg = tanhf(g2.z), og = sigmoidf(g3.z);
      cc.z = fg * c0v.z + ig * gg; hh.z = og * tanhf(cc.z); }
    { float ig = sigmoidf(g0.w), fg = sigmoidf(g1.w), gg = tanhf(g2.w), og = sigmoidf(g3.w);
      cc.w = fg * c0v.w + ig * gg; hh.w = og * tanhf(cc.w); }
    ((float4*)c1)[idx] = cc;
    ((float4*)h1)[idx] = hh;
}

// ---------------- K_select (mode1: ctx side) ----------------
__global__ void k_select(const float* __restrict__ weights, const float* __restrict__ lmask,
                         const float* __restrict__ land, int* __restrict__ out_idx,
                         float* __restrict__ out_rows, float* __restrict__ out_norm,
                         const float* __restrict__ lrel_src, const float* __restrict__ rmask_src,
                         float* __restrict__ out_lrel, float* __restrict__ out_rmask, int mode)
{
    int b = blockIdx.x;
    int t = threadIdx.x;  // 128
    __shared__ float v[Mm];
    __shared__ int bidx[TOPN];
    __shared__ float red[128];

    v[t] = weights[b * CFG + (t >> 3)] * lmask[b * Mm + t];
    __syncthreads();
    if (t == 0) {
        for (int rep = 0; rep < TOPN; rep++) {
            float bv = v[0]; int bi = 0;
            for (int m = 1; m < Mm; m++) { float x = v[m]; if (x > bv) { bv = x; bi = m; } }
            bidx[rep] = bi; v[bi] = -3.4e38f;
        }
    }
    __syncthreads();
    if (t < TOPN) out_idx[b * TOPN + t] = bidx[t];

    for (int tt = 0; tt < TOPN; tt++) {
        int m = bidx[tt];
        const float4* src = (const float4*)(land + ((size_t)(b * Mm + m)) * Dd);
        float4* dst = (float4*)(out_rows + ((size_t)(b * TOPN + tt)) * Dd);
        float part = 0.f;
        for (int j = t; j < D4; j += 128) {
            float4 x = src[j];
            dst[j] = x;
            part += dot4(x, x);
        }
        red[t] = part; __syncthreads();
        for (int off = 64; off > 0; off >>= 1) { if (t < off) red[t] += red[t + off]; __syncthreads(); }
        if (t == 0) out_norm[b * TOPN + tt] = sqrtf(red[0]);
        __syncthreads();
    }

    if (mode == 1) {
        if (t < TOPN * 6) {
            int tt = t / 6, r = t % 6;
            out_lrel[(b * TOPN + tt) * 6 + r] = lrel_src[((size_t)(b * Mm + bidx[tt])) * 6 + r];
        }
        if (t < TOPN) out_rmask[b * TOPN + t] = rmask_src[b * Mm + bidx[t]];
    }
}

// ---------------- K_select_act: blocks [0,Bz)=select(mode0); [Bz,2Bz)=actemb ----------------
__global__ void k_select_act(const float* __restrict__ weights, const float* __restrict__ lmask,
                             const float* __restrict__ land, int* __restrict__ out_idx,
                             float* __restrict__ out_rows, float* __restrict__ out_norm,
                             const float* __restrict__ action, const float* __restrict__ embW,
                             const float* __restrict__ embb, float* __restrict__ x)
{
    int t = threadIdx.x;  // 128
    if (blockIdx.x >= Bz) {
        int b = blockIdx.x - Bz;
        if (t < EMB) {
            float acc = 0.f;
            #pragma unroll 4
            for (int a = 0; a < ANG; a++) acc += action[b * ANG + a] * embW[a * EMB + t];
            x[(size_t)b * XDIM + t] = tanhf(acc + embb[t]);
        }
        return;
    }
    int b = blockIdx.x;
    __shared__ float v[Mm];
    __shared__ int bidx[TOPN];
    __shared__ float red[128];

    v[t] = weights[b * CFG + (t >> 3)] * lmask[b * Mm + t];
    __syncthreads();
    if (t == 0) {
        for (int rep = 0; rep < TOPN; rep++) {
            float bv = v[0]; int bi = 0;
            for (int m = 1; m < Mm; m++) { float xx = v[m]; if (xx > bv) { bv = xx; bi = m; } }
            bidx[rep] = bi; v[bi] = -3.4e38f;
        }
    }
    __syncthreads();
    if (t < TOPN) out_idx[b * TOPN + t] = bidx[t];

    for (int tt = 0; tt < TOPN; tt++) {
        int m = bidx[tt];
        const float4* src = (const float4*)(land + ((size_t)(b * Mm + m)) * Dd);
        float4* dst = (float4*)(out_rows + ((size_t)(b * TOPN + tt)) * Dd);
        float part = 0.f;
        for (int j = t; j < D4; j += 128) {
            float4 xx = src[j];
            dst[j] = xx;
            part += dot4(xx, xx);
        }
        red[t] = part; __syncthreads();
        for (int off = 64; off > 0; off >>= 1) { if (t < off) red[t] += red[t + off]; __syncthreads(); }
        if (t == 0) out_norm[b * TOPN + tt] = sqrtf(red[0]);
        __syncthreads();
    }
}

// ---------------- K_pano ----------------
__global__ void k_pano(const float* __restrict__ pano_obj, const float* __restrict__ land_sel,
                       const float* __restrict__ land_norm, float* __restrict__ pano_sim)
{
    int b = blockIdx.y, p = blockIdx.x;
    int tid = threadIdx.x;              // 256
    int warp = tid >> 5, lane = tid & 31;
    __shared__ float4 land4[TOPN * D4];
    __shared__ float lnorm[TOPN];
    __shared__ float sim[OBJ][TOPN];
    __shared__ int best[TOPN];

    const float4* ls4 = (const float4*)(land_sel + (size_t)b * TOPN * Dd);
    for (int idx = tid; idx < TOPN * D4; idx += 256) land4[idx] = ls4[idx];
    if (tid < TOPN) lnorm[tid] = land_norm[b * TOPN + tid];
    __syncthreads();

    const float* obase = pano_obj + ((size_t)(b * PANO + p)) * OBJ * Dd;
    for (int o = warp; o < OBJ; o += 8) {
        const float4* row4 = (const float4*)(obase + (size_t)o * Dd);
        float a0 = 0, a1 = 0, a2 = 0, an = 0;
        for (int j = lane; j < D4; j += 32) {
            float4 f = row4[j];
            a0 += dot4(f, land4[j]);
            a1 += dot4(f, land4[D4 + j]);
            a2 += dot4(f, land4[2 * D4 + j]);
            an += dot4(f, f);
        }
        a0 = warp_sum(a0); a1 = warp_sum(a1); a2 = warp_sum(a2); an = warp_sum(an);
        if (lane == 0) {
            float no = sqrtf(an);
            sim[o][0] = a0 / fmaxf(no * lnorm[0], EPSV);
            sim[o][1] = a1 / fmaxf(no * lnorm[1], EPSV);
            sim[o][2] = a2 / fmaxf(no * lnorm[2], EPSV);
        }
    }
    __syncthreads();
    if (tid < TOPN) {
        float bv = sim[0][tid]; int bi = 0;
        for (int o = 1; o < OBJ; o++) { float s = sim[o][tid]; if (s > bv) { bv = s; bi = o; } }
        best[tid] = bi;
    }
    __syncthreads();
    float4* dst = (float4*)(pano_sim + ((size_t)(b * PANO + p)) * TOPN * Dd);
    for (int idx = tid; idx < TOPN * D4; idx += 256) {
        int tt = idx / D4, j = idx % D4;
        dst[idx] = ((const float4*)(obase + (size_t)best[tt] * Dd))[j];
    }
}

// ---------------- K_attn_logits: one (b,s) dot per block ----------------
__global__ void k_attn_logits(const float* __restrict__ feature, const float* __restrict__ pano_sim,
                              const float* __restrict__ qf, float* __restrict__ aval)
{
    int s = blockIdx.x, b = blockIdx.y;
    int tid = threadIdx.x; // 256
    __shared__ float red[256];
    const float4* f4  = (const float4*)(feature + ((size_t)(b * PANO + s)) * FEAT);
    const float4* ps4 = (const float4*)(pano_sim + ((size_t)(b * PANO + s)) * TOPN * Dd);
    const float4* q4  = (const float4*)(qf + (size_t)b * FEAT_ALL);
    float acc = 0.f;
    for (int j = tid; j < F4F; j += 256) acc += dot4(f4[j], q4[j]);
    for (int j = tid; j < F4P; j += 256) acc += dot4(ps4[j], q4[F4F + j]);
    red[tid] = acc; __syncthreads();
    for (int off = 128; off > 0; off >>= 1) { if (tid < off) red[tid] += red[tid + off]; __syncthreads(); }
    if (tid == 0) aval[b * PANO + s] = red[0];
}

// ---------------- K_attn_feat: fused softmax(aval) + weighted sum ----------------
__global__ void k_attn_feat(const float* __restrict__ feature, const float* __restrict__ pano_sim,
                            const float* __restrict__ aval, float* __restrict__ x)
{
    int b = blockIdx.y;
    int j = blockIdx.x * 128 + threadIdx.x;
    __shared__ float p[PANO];
    if (threadIdx.x < PANO) p[threadIdx.x] = aval[b * PANO + threadIdx.x];
    __syncthreads();
    if (threadIdx.x == 0) {
        float mx = p[0];
        for (int s = 1; s < PANO; s++) mx = fmaxf(mx, p[s]);
        float sum = 0.f;
        for (int s = 0; s < PANO; s++) { float e = expf(p[s] - mx); p[s] = e; sum += e; }
        float inv = 1.0f / sum;
        for (int s = 0; s < PANO; s++) p[s] *= inv;
    }
    __syncthreads();
    if (j >= F4A) return;
    float4 acc = make_float4(0.f, 0.f, 0.f, 0.f);
    if (j < F4F) {
        const float4* f4 = (const float4*)(feature + (size_t)b * PANO * FEAT) + j;
        #pragma unroll 4
        for (int s = 0; s < PANO; s++) {
            float4 v = f4[(size_t)s * F4F];
            float w = p[s];
            acc.x += w * v.x; acc.y += w * v.y; acc.z += w * v.z; acc.w += w * v.w;
        }
    } else {
        const float4* f4 = (const float4*)(pano_sim + (size_t)b * PANO * TOPN * Dd) + (j - F4F);
        #pragma unroll 4
        for (int s = 0; s < PANO; s++) {
            float4 v = f4[(size_t)s * F4P];
            float w = p[s];
            acc.x += w * v.x; acc.y += w * v.y; acc.z += w * v.z; acc.w += w * v.w;
        }
    }
    ((float4*)(x + (size_t)b * XDIM + EMB))[j] = acc;
}

// ---------------- K_ctx ----------------
__global__ void k_ctx(const float* __restrict__ ctx, const float* __restrict__ part,
                      const float* __restrict__ h1, float* __restrict__ ctx_attn,
                      float* __restrict__ cat, int S)
{
    int b = blockIdx.x;
    int tid = threadIdx.x, warp = tid >> 5, lane = tid & 31; // 512 threads
    __shared__ float4 q2s[128];
    __shared__ float lg[CFG];
    __shared__ float pr[CFG];

    if (tid < 128) {
        const float4* p4 = (const float4*)part;
        float4 s = make_float4(0.f, 0.f, 0.f, 0.f);
        for (int ss = 0; ss < S; ss++)
            s = f4add(s, p4[(size_t)(ss * Bz + b) * 128 + tid]);
        q2s[tid] = s;
    }
    __syncthreads();
    {
        int s = warp;
        const float4* c4 = (const float4*)(ctx + ((size_t)(b * CFG + s)) * Hh);
        float acc = 0.f;
        for (int j = lane; j < 128; j += 32) acc += dot4(c4[j], q2s[j]);
        acc = warp_sum(acc);
        if (lane == 0) lg[s] = acc;
    }
    __syncthreads();
    if (tid == 0) {
        float mx = lg[0];
        for (int s = 1; s < CFG; s++) mx = fmaxf(mx, lg[s]);
        float sum = 0.f;
        for (int s = 0; s < CFG; s++) { float e = expf(lg[s] - mx); pr[s] = e; sum += e; }
        float inv = 1.0f / sum;
        for (int s = 0; s < CFG; s++) pr[s] *= inv;
    }
    __syncthreads();
    if (tid < CFG) ctx_attn[b * CFG + tid] = pr[tid];
    if (tid < 128) {
        const float4* c4 = (const float4*)(ctx + (size_t)b * CFG * Hh) + tid;
        float4 acc = make_float4(0.f, 0.f, 0.f, 0.f);
        #pragma unroll
        for (int s = 0; s < CFG; s++) {
            float4 v = c4[(size_t)s * 128];
            float w = pr[s];
            acc.x += w * v.x; acc.y += w * v.y; acc.z += w * v.z; acc.w += w * v.w;
        }
        ((float4*)(cat + (size_t)b * 2 * Hh))[tid] = acc;
        ((float4*)(cat + (size_t)b * 2 * Hh + Hh))[tid] = ((const float4*)(h1 + (size_t)b * Hh))[tid];
    }
}

// ---------------- K_logit ----------------
__global__ void k_logit(const float* __restrict__ cand_obj, const float* __restrict__ cland,
                        const float* __restrict__ cland_norm, const float* __restrict__ cand_feat,
                        const float* __restrict__ crel_in, const float* __restrict__ lrel,
                        const float* __restrict__ rmask, const float* __restrict__ q3,
                        float* __restrict__ logit)
{
    int b = blockIdx.y, i = blockIdx.x;
    int tid = threadIdx.x, warp = tid >> 5, lane = tid & 31; // 256
    __shared__ float4 land4[TOPN * D4];
    __shared__ float lnorm[TOPN];
    __shared__ float sim[OBJ][TOPN];
    __shared__ int best[TOPN];
    __shared__ float red[256];

    const float4* ls4 = (const float4*)(cland + (size_t)b * TOPN * Dd);
    for (int idx = tid; idx < TOPN * D4; idx += 256) land4[idx] = ls4[idx];
    if (tid < TOPN) lnorm[tid] = cland_norm[b * TOPN + tid];
    __syncthreads();

    const float* obase = cand_obj + ((size_t)(b * IMG + i)) * OBJ * Dd;
    for (int o = warp; o < OBJ; o += 8) {
        const float4* row4 = (const float4*)(obase + (size_t)o * Dd);
        float a0 = 0, a1 = 0, a2 = 0, an = 0;
        for (int j = lane; j < D4; j += 32) {
            float4 f = row4[j];
            a0 += dot4(f, land4[j]);
            a1 += dot4(f, land4[D4 + j]);
            a2 += dot4(f, land4[2 * D4 + j]);
            an += dot4(f, f);
        }
        a0 = warp_sum(a0); a1 = warp_sum(a1); a2 = warp_sum(a2); an = warp_sum(an);
        if (lane == 0) {
            float no = sqrtf(an);
            sim[o][0] = a0 / fmaxf(no * lnorm[0], EPSV);
            sim[o][1] = a1 / fmaxf(no * lnorm[1], EPSV);
            sim[o][2] = a2 / fmaxf(no * lnorm[2], EPSV);
        }
    }
    __syncthreads();
    if (tid < TOPN) {
        float bv = sim[0][tid]; int bi = 0;
        for (int o = 1; o < OBJ; o++) { float s = sim[o][tid]; if (s > bv) { bv = s; bi = o; } }
        best[tid] = bi;
    }
    __syncthreads();

    const float* q = q3 + (size_t)b * CAND_PAD;
    const float4* q4 = (const float4*)q;
    const float4* cf4 = (const float4*)(cand_feat + ((size_t)(b * IMG + i)) * FEAT);
    float part = 0.f;
    for (int j = tid; j < F4F; j += 256) part += dot4(cf4[j], q4[j]);
    for (int idx = tid; idx < TOPN * D4; idx += 256) {
        int tt = idx / D4, j = idx % D4;
        float4 f = ((const float4*)(obase + (size_t)best[tt] * Dd))[j];
        const float* qs = q + FEAT + tt * (Dd + 7) + j * 4;
        part += f.x * qs[0] + f.y * qs[1] + f.z * qs[2] + f.w * qs[3];
    }
    red[tid] = part; __syncthreads();
    for (int off = 128; off > 0; off >>= 1) { if (tid < off) red[tid] += red[tid + off]; __syncthreads(); }
    if (tid == 0) {
        float s = red[0];
        const float* cr = crel_in + ((size_t)(b * IMG + i)) * 6;
        for (int tt = 0; tt < TOPN; tt++) {
            const float* qs = q + FEAT + tt * (Dd + 7);
            float rm = rmask[b * TOPN + tt];
            float lor = 0.f;
            #pragma unroll
            for (int r = 0; r < 6; r++) {
                lor += cr[r] * lrel[(b * TOPN + tt) * 6 + r];
                s += cr[r] * rm * qs[Dd + r];
            }
            s += lor * qs[Dd + 6];
        }
        logit[b * IMG + i] = s;
    }
}

// ---------------- launch (single stream; minimal splits subject to nk>=2) ----------------
extern "C" void kernel_launch(void* const* d_in, const int* in_sizes, int n_in,
                              void* d_out, int out_size)
{
    const float* action     = (const float*)d_in[0];
    const float* feature    = (const float*)d_in[1];
    const float* cand_feat  = (const float*)d_in[2];
    const float* prev_h1    = (const float*)d_in[3];
    const float* c_0        = (const float*)d_in[4];
    const float* ctx        = (const float*)d_in[5];
    const float* s_0        = (const float*)d_in[6];
    const float* land       = (const float*)d_in[7];
    const float* cand_obj   = (const float*)d_in[8];
    const float* lmask      = (const float*)d_in[9];
    const float* lrel_in    = (const float*)d_in[10];
    const float* rmask_in   = (const float*)d_in[11];
    const float* crel_in    = (const float*)d_in[12];
    const float* pano_obj   = (const float*)d_in[13];
    const float* embW       = (const float*)d_in[14];
    const float* embb       = (const float*)d_in[15];
    const float* W_ih       = (const float*)d_in[16];
    const float* W_hh       = (const float*)d_in[17];
    const float* b_lstm     = (const float*)d_in[18];
    const float* feat_in_W  = (const float*)d_in[19];
    const float* att_in_W   = (const float*)d_in[20];
    const float* att_out_W  = (const float*)d_in[21];
    const float* cand_in_W  = (const float*)d_in[22];

    float* out   = (float*)d_out;
    float* h1    = out;
    float* c1    = out + Bz * Hh;
    float* logit = out + 2 * Bz * Hh;
    float* ht    = out + 2 * Bz * Hh + Bz * IMG;
    float* ctxa  = ht + Bz * Hh;

    int   *p_top, *p_ctop;
    float *p_lsel, *p_lnorm, *p_cland, *p_clnorm, *p_lrel, *p_rmask, *p_psim;
    float *p_qf, *p_av, *p_x, *p_cat, *p_qc, *p_part;
    cudaGetSymbolAddress((void**)&p_top,    g_top_idx);
    cudaGetSymbolAddress((void**)&p_ctop,   g_ctop);
    cudaGetSymbolAddress((void**)&p_lsel,   g_land_sel);
    cudaGetSymbolAddress((void**)&p_lnorm,  g_land_norm);
    cudaGetSymbolAddress((void**)&p_cland,  g_cland);
    cudaGetSymbolAddress((void**)&p_clnorm, g_cland_norm);
    cudaGetSymbolAddress((void**)&p_lrel,   g_lrel);
    cudaGetSymbolAddress((void**)&p_rmask,  g_rmask);
    cudaGetSymbolAddress((void**)&p_psim,   g_pano_sim);
    cudaGetSymbolAddress((void**)&p_qf,     g_q_feat);
    cudaGetSymbolAddress((void**)&p_av,     g_aval);
    cudaGetSymbolAddress((void**)&p_x,      g_x);
    cudaGetSymbolAddress((void**)&p_cat,    g_cat);
    cudaGetSymbolAddress((void**)&p_qc,     g_q_cand);
    cudaGetSymbolAddress((void**)&p_part,   g_part);

    // 1. top-3 landmark selection from s_0 + action embedding (merged launch)
    k_select_act<<<2 * Bz, 128>>>(s_0, lmask, land, p_top, p_lsel, p_lnorm,
                                  action, embW, embb, p_x);
    // 2. pano cosine argmax + gather
    k_pano<<<dim3(PANO, Bz), 256>>>(pano_obj, p_lsel, p_lnorm, p_psim);
    // 3. dual GEMM: q_feat (Kc=64 S=8, splits 0..7) + W_hh (Kc=64 S=8, splits 25..32); KT=16 nk=4
    gemm64w_dual<<<328, 128>>>(prev_h1, feat_in_W, Hh, FEAT_ALL, FEAT_ALL, 64, 0, 25, 200,
                               prev_h1, W_hh, Hh, G4, G4, 64, 25, 16, p_part);
    k_combine<<<(Bz * F4A + 255) / 256, 256>>>(p_part, p_qf, Bz * F4A, 8, Bz * F4A, 0);
    // 4. attention logits (full-chip parallel); softmax fused into attn_feat
    k_attn_logits<<<dim3(PANO, Bz), 256>>>(feature, p_psim, p_qf, p_av);
    // 5. attn_feat (fused softmax) -> x[:, 64:]
    k_attn_feat<<<dim3((F4A + 127) / 128, Bz), 128>>>(feature, p_psim, p_av, p_x);
    // 6. W_ih GEMM (KT=32, splits 0..19, Kc=160 nk=5), then fused cell over two split ranges
    gemm64w<32, true><<<dim3(16, 20), 128>>>(p_x, W_ih, p_part, XDIM, G4, G4, G4, 160, 0);
    k_combine_cell<<<(Bz * Hh / 4 + 255) / 256, 256>>>(p_part, b_lstm, c_0, h1, c1, 20, 25, 8);
    // 7. q2 partials (KT=32, Kc=64 S=8 nk=2) + ctx attention (fused combine, S=8)
    gemm64w<32, true><<<dim3(4, 8), 128>>>(h1, att_in_W, p_part, Hh, Hh, Hh, Hh, 64, 0);
    k_ctx<<<Bz, 512>>>(ctx, p_part, h1, ctxa, p_cat, 8);
    // 8. h_tilde = tanh([wctx,h1] @ att_out_W)  (KT=32, Kc=128 S=8 nk=4)
    gemm64w<32, true><<<dim3(4, 8), 128>>>(p_cat, att_out_W, p_part, 2 * Hh, Hh, Hh, Hh, 128, 0);
    k_combine<<<(Bz * Hh / 4 + 255) / 256, 256>>>(p_part, ht, Bz * Hh / 4, 8, Bz * Hh / 4, 1);
    // 9. top-3 from ctx_attn + relation gathers
    k_select<<<Bz, 128>>>(ctxa, lmask, land, p_ctop, p_cland, p_clnorm,
                          lrel_in, rmask_in, p_lrel, p_rmask, 1);
    // 10. q3 (KT=32, Kc=64 S=8 nk=2; N=3097 odd -> scalar W loads)
    gemm64w<32, false><<<dim3(25, 8), 128>>>(ht, cand_in_W, p_part, Hh, CAND_ALL, 3100, CAND_PAD, 64, 0);
    k_combine<<<(Bz * CAND_PAD / 4 + 255) / 256, 256>>>(p_part, p_qc, Bz * CAND_PAD / 4, 8, Bz * CAND_PAD / 4, 0);
    // 11. candidate argmax + logits
    k_logit<<<dim3(IMG, Bz), 256>>>(cand_obj, p_cland, p_clnorm, cand_feat,
                                    crel_in, p_lrel, p_rmask, p_qc, logit);
}